// round 15
// baseline (speedup 1.0000x reference)
#include <cuda_runtime.h>
#include <math_constants.h>

#define V 100000
#define H 256
#define T_STEPS 64
#define NB 296                /* 2 CTAs per SM; CTA0 = coordinator (no rows) */
#define TPB 512
#define NWARP 16
#define RPC 339               /* 295*339 = 100005 >= V, CTAs 1..295 hold rows */
#define KTOP 10
#define NCAND (NB*KTOP)       /* 2960 */
#define CPT 6                 /* ceil(NCAND/TPB) */
#define HPC 3
#define NGRU 86               /* GRU CTAs: c in [1,86] */
#define SROWS 82              /* fc rows cached in dynamic smem per CTA */
#define DSMEM_BYTES (SROWS*H*4)

#define OUT_SEL   ((size_t)T_STEPS * V)
#define OUT_VAL   (OUT_SEL + T_STEPS)
#define OUT_HIT   (OUT_VAL + T_STEPS)
#define OUT_HIST  (OUT_HIT + T_STEPS)

// ---------------- device scratch ----------------
__device__ __align__(16) float g_cell[H];
__device__ __align__(16) float g_proc[H];
__device__ __align__(16) float g_xb[H];
__device__ __align__(16) float g_xc[H];
__device__ float g_blkmax[NB];
__device__ float g_blksum[NB];
__device__ float g_candv[NCAND];
__device__ int   g_candi[NCAND];      // packed (idx<<1)|interesting
__device__ float g_biv[NB];           // per-block best-interesting value
__device__ int   g_bii[NB];           // per-block best-interesting packed id
__device__ float g_gmaxS, g_invZS;
__device__ unsigned g_selP;           // (t+1)<<18 | (sel<<1) | hit
__device__ unsigned g_cnt0, g_cnt1, g_cntA, g_cntB, g_cntC;
__device__ unsigned g_nrmF;

__device__ __forceinline__ float sigmoidf_(float x){ return 1.f/(1.f+expf(-x)); }
__device__ __forceinline__ float dot8(float4 a, float4 b, float4 x, float4 y){
  return a.x*x.x + a.y*x.y + a.z*x.z + a.w*x.w
       + b.x*y.x + b.y*y.y + b.z*y.z + b.w*y.w;
}

// scoped release/acquire primitives
__device__ __forceinline__ void red_release(unsigned* p, unsigned v){
  asm volatile("red.release.gpu.global.add.u32 [%0], %1;" :: "l"(p), "r"(v) : "memory");
}
__device__ __forceinline__ void st_release(unsigned* p, unsigned v){
  asm volatile("st.release.gpu.global.u32 [%0], %1;" :: "l"(p), "r"(v) : "memory");
}
__device__ __forceinline__ unsigned ld_acquire(unsigned* p){
  unsigned v;
  asm volatile("ld.acquire.gpu.global.u32 %0, [%1];" : "=r"(v) : "l"(p) : "memory");
  return v;
}
#define WAIT_ACQ(ptr, tgt) while (ld_acquire(&(ptr)) < (tgt)) {}

// fc_W loads: L2 evict_last policy (pin resident)
__device__ __forceinline__ float4 ldg_el(const float4* p, unsigned long long pol){
  float4 v;
  asm("ld.global.L2::cache_hint.v4.f32 {%0,%1,%2,%3}, [%4], %5;"
      : "=f"(v.x), "=f"(v.y), "=f"(v.z), "=f"(v.w)
      : "l"(p), "l"(pol));
  return v;
}

__global__ __launch_bounds__(TPB) void k_reset(){
  if (threadIdx.x == 0){
    g_cnt0 = 0u; g_cnt1 = 0u; g_cntA = 0u; g_cntB = 0u; g_cntC = 0u;
    g_selP = 0u; g_nrmF = 0u;
  }
}

// shfl block reductions
__device__ __forceinline__ float blockMaxB(float v, float* sw){
  int lane = threadIdx.x & 31, warp = threadIdx.x >> 5;
  #pragma unroll
  for (int o=16; o; o>>=1) v = fmaxf(v, __shfl_down_sync(0xffffffffu, v, o));
  if (lane == 0) sw[warp] = v;
  __syncthreads();
  if (warp == 0){
    float x = (lane < NWARP) ? sw[lane] : -CUDART_INF_F;
    #pragma unroll
    for (int o=8; o; o>>=1) x = fmaxf(x, __shfl_down_sync(0xffffffffu, x, o));
    if (lane == 0) sw[0] = x;
  }
  __syncthreads();
  float r = sw[0];
  __syncthreads();
  return r;
}
__device__ __forceinline__ float blockSumB(float v, float* sw){
  int lane = threadIdx.x & 31, warp = threadIdx.x >> 5;
  #pragma unroll
  for (int o=16; o; o>>=1) v += __shfl_down_sync(0xffffffffu, v, o);
  if (lane == 0) sw[warp] = v;
  __syncthreads();
  if (warp == 0){
    float x = (lane < NWARP) ? sw[lane] : 0.f;
    #pragma unroll
    for (int o=8; o; o>>=1) x += __shfl_down_sync(0xffffffffu, x, o);
    if (lane == 0) sw[0] = x;
  }
  __syncthreads();
  float r = sw[0];
  __syncthreads();
  return r;
}

// 9 warps: dots for 3 h x 3 gates (weights smem, x smem)
__device__ __forceinline__ void gru_dots(const float* Wsm, const float* sx, float* sgx, int gc){
  int tid = threadIdx.x, lane = tid & 31, warp = tid >> 5;
  if (warp < 3*HPC){
    int a = warp / 3;
    int h = gc*HPC + a;
    float s = 0.f;
    if (h < H){
      const float4* wr = (const float4*)(Wsm + warp*H);
      const float4* xr = (const float4*)sx;
      s = dot8(wr[lane], wr[lane+32], xr[lane], xr[lane+32]);
    }
    #pragma unroll
    for (int o=16; o; o>>=1) s += __shfl_down_sync(0xffffffffu, s, o);
    if (lane == 0) sgx[warp] = s;
  }
  __syncthreads();
}
__device__ __forceinline__ void gru_act(const float* sgx,
                                        const float* bi, const float* bh,
                                        float* xout_g, int gc){
  int tid = threadIdx.x;
  if (tid < HPC){
    int h = gc*HPC + tid;
    if (h < H){
      float r = sigmoidf_(sgx[tid*3+0] + bi[h]     + bh[h]);
      float z = sigmoidf_(sgx[tid*3+1] + bi[H+h]   + bh[H+h]);
      float n = tanhf   (sgx[tid*3+2] + bi[2*H+h] + r*bh[2*H+h]);
      xout_g[h] = (1.f - z) * n;
    }
  }
  __syncthreads();
}

__global__ __launch_bounds__(TPB, 2)
void k_persist(const float* __restrict__ interesting, const float* __restrict__ masking,
               const float* __restrict__ mem, const float* __restrict__ emb,
               const float* __restrict__ Wih, const float* __restrict__ bih,
               const float* __restrict__ bhh, const float* __restrict__ fcW,
               const float* __restrict__ fcb, const float* __restrict__ valW,
               const float* __restrict__ valb, const float* __restrict__ memW,
               const float* __restrict__ fgmW, const float* __restrict__ fgmb,
               const float* __restrict__ fgcW, float* __restrict__ out){
  extern __shared__ __align__(16) float s_wfc[];   // SROWS*H fc rows (dynamic)
  __shared__ __align__(16) float scell[H];
  __shared__ __align__(16) float sx[H];
  __shared__ float sb[RPC];
  __shared__ float slogit[RPC];
  __shared__ float s_hist[RPC];
  __shared__ unsigned char s_int[RPC];
  __shared__ __align__(16) float w0[3*HPC*H];
  __shared__ __align__(16) float w1[3*HPC*H];
  __shared__ __align__(16) float wg[HPC*H];
  __shared__ float swv[NWARP];
  __shared__ int   swi[NWARP];
  __shared__ float swv2[NWARP];
  __shared__ int   swi2[NWARP];
  __shared__ float swm[NWARP];     // per-warp online max
  __shared__ float swz[NWARP];     // per-warp online sum
  __shared__ float swtv[NWARP*KTOP];
  __shared__ int   swti[NWARP*KTOP];
  __shared__ float sbiv[NWARP];
  __shared__ int   sbii[NWARP];
  __shared__ float sgx[3*HPC];
  __shared__ float sgbias[HPC];
  __shared__ float sprocL[HPC];
  __shared__ float s_gm, s_iz, s_sign;
  __shared__ int   s_sel;

  const int tid = threadIdx.x, lane = tid & 31, warp = tid >> 5;
  const int c = blockIdx.x;
  const int gc = c - 1;
  const bool isGru = (c >= 1 && c <= NGRU);
  const int base = (c == 0) ? 0 : (c-1) * RPC;
  const int myRows = (c == 0) ? 0 : min(RPC, V - (c-1)*RPC);

  unsigned long long pol;
  asm("createpolicy.fractional.L2::evict_last.b64 %0, 1.0;" : "=l"(pol));

  // ---------- prologue loads ----------
  for (int i = tid; i < myRows; i += TPB){
    sb[i] = fcb[base + i];
    s_hist[i] = masking[base + i];
    s_int[i] = (interesting[base + i] > 0.f) ? 1 : 0;
  }
  if (c != 0){
    const float4* src = (const float4*)(fcW + (size_t)base*H);
    float4* dst = (float4*)s_wfc;
    for (int i = tid; i < SROWS*H/4; i += TPB) dst[i] = __ldcs(&src[i]);
  }
  if (c == 0){
    if (tid == 0){ g_blkmax[0] = -CUDART_INF_F; g_blksum[0] = 0.f;
                   g_biv[0] = -CUDART_INF_F; g_bii[0] = 0x7FFFFFFF; }
    if (tid < KTOP){ g_candv[tid] = -CUDART_INF_F; g_candi[tid] = 0x7FFFFFFF; }
  }
  if (isGru){
    for (int idx = tid; idx < 3*HPC*H; idx += TPB){
      int j = idx / H, col = idx % H;
      int a = j / 3, g = j % 3, h = gc*HPC + a;
      float v0 = 0.f, v1 = 0.f;
      if (h < H){
        v0 = Wih[(size_t)(g*H + h)*H + col];
        v1 = Wih[(size_t)3*H*H + (size_t)(g*H + h)*H + col];
      }
      w0[idx] = v0; w1[idx] = v1;
    }
    for (int idx = tid; idx < HPC*H; idx += TPB){
      int a = idx / H, col = idx % H, h = gc*HPC + a;
      wg[idx] = (h < H) ? fgcW[(size_t)h*H + col] : 0.f;
    }
  }
  // proc row r = c (c < 256)
  for (int r = c; r < H; r += NB){
    const float4* m4 = (const float4*)mem;
    const float4* w4 = (const float4*)(memW + (size_t)r*V);
    float s = 0.f;
    for (int i = tid; i < V/4; i += TPB){
      float4 a = m4[i], b = __ldcs(&w4[i]);
      s += a.x*b.x + a.y*b.y + a.z*b.z + a.w*b.w;
    }
    s = blockSumB(s, swv);
    if (tid == 0){ g_proc[r] = tanhf(s); }
  }
  __syncthreads();
  if (tid == 0) red_release(&g_cnt0, 1u);

  // ---------- prologue GRU: cell(0) from x = emb row 0 ----------
  if (isGru){
    if (tid == 0){ WAIT_ACQ(g_cnt0, (unsigned)NB); }
    __syncthreads();
    if (tid < H) sx[tid] = __ldcg(&g_proc[tid]);
    __syncthreads();
    if (warp < HPC){
      int h = gc*HPC + warp;
      if (h < H){
        const float4* wr = (const float4*)(fgmW + (size_t)h*H);
        const float4* xr = (const float4*)sx;
        float s = dot8(wr[lane], wr[lane+32], xr[lane], xr[lane+32]);
        #pragma unroll
        for (int o=16; o; o>>=1) s += __shfl_down_sync(0xffffffffu, s, o);
        if (lane == 0) sgbias[warp] = -(s + fgmb[h]);
      }
    }
    if (tid < HPC){
      int h = gc*HPC + tid;
      sprocL[tid] = (h < H) ? sx[h] : 0.f;
    }
    __syncthreads();
    if (tid < H) sx[tid] = __ldg(&emb[tid]);
    __syncthreads();
    gru_dots(w0, sx, sgx, gc);
    gru_act(sgx, bih, bhh, g_xb, gc);
    if (tid == 0){ red_release(&g_cntA, 1u); WAIT_ACQ(g_cntA, (unsigned)NGRU); }
    __syncthreads();
    if (tid < H) sx[tid] = __ldcg(&g_xb[tid]);
    __syncthreads();
    gru_dots(w1, sx, sgx, gc);
    gru_act(sgx, bih + 3*H, bhh + 3*H, g_xc, gc);
    if (tid == 0){ red_release(&g_cntB, 1u); WAIT_ACQ(g_cntB, (unsigned)NGRU); }
    __syncthreads();
    if (tid < H) sx[tid] = __ldcg(&g_xc[tid]);
    __syncthreads();
    if (warp < HPC){
      int h = gc*HPC + warp;
      float s = 0.f;
      if (h < H){
        const float4* wr = (const float4*)(wg + warp*H);
        const float4* xr = (const float4*)sx;
        s = dot8(wr[lane], wr[lane+32], xr[lane], xr[lane+32]);
      }
      #pragma unroll
      for (int o=16; o; o>>=1) s += __shfl_down_sync(0xffffffffu, s, o);
      if (lane == 0) sgx[warp] = s;
    }
    __syncthreads();
    if (tid < HPC){
      int h = gc*HPC + tid;
      if (h < H){
        float gate = sigmoidf_(sgbias[tid] + sgx[tid]);
        g_cell[h] = gate*sprocL[tid] + (1.f-gate)*sx[h];
      }
    }
    __syncthreads();
    if (tid == 0) red_release(&g_cntC, 1u);
  }

  // ---------- main loop ----------
  for (int t = 0; t < T_STEPS; t++){
    if (tid == 0){ WAIT_ACQ(g_cntC, 86u*(unsigned)(t+1)); }
    __syncthreads();
    if (tid < H) scell[tid] = __ldcg(&g_cell[tid]);
    __syncthreads();

    if (c != 0){
      const float4* sc4 = (const float4*)scell;
      float4 c0 = sc4[lane], c1 = sc4[lane+32];
      // per-warp online softmax stats (lane 0)
      float wm = -CUDART_INF_F, wz = 0.f;
      // part 1: smem-resident rows
      for (int r = warp; r < SROWS; r += NWARP){
        const float4* wr = (const float4*)(s_wfc + r*H);
        float s = dot8(wr[lane], wr[lane+32], c0, c1);
        #pragma unroll
        for (int o=16; o; o>>=1) s += __shfl_down_sync(0xffffffffu, s, o);
        if (lane == 0){
          float lg = s + sb[r];
          slogit[r] = lg;
          float nm = fmaxf(wm, lg);
          wz = wz*__expf(wm-nm) + __expf(lg-nm);
          wm = nm;
        }
      }
      // part 2: L2-resident rows, 4 in flight, evict_last
      for (int r = SROWS + warp; r < myRows; r += NWARP*4){
        int r1 = r + NWARP, r2 = r + 2*NWARP, r3 = r + 3*NWARP;
        int q1 = min(r1, myRows-1), q2 = min(r2, myRows-1), q3 = min(r3, myRows-1);
        const float4* p0 = (const float4*)(fcW + (size_t)(base + r )*H);
        const float4* p1 = (const float4*)(fcW + (size_t)(base + q1)*H);
        const float4* p2 = (const float4*)(fcW + (size_t)(base + q2)*H);
        const float4* p3 = (const float4*)(fcW + (size_t)(base + q3)*H);
        float4 a0 = ldg_el(p0 + lane, pol), b0 = ldg_el(p0 + lane + 32, pol);
        float4 a1 = ldg_el(p1 + lane, pol), b1 = ldg_el(p1 + lane + 32, pol);
        float4 a2 = ldg_el(p2 + lane, pol), b2 = ldg_el(p2 + lane + 32, pol);
        float4 a3 = ldg_el(p3 + lane, pol), b3 = ldg_el(p3 + lane + 32, pol);
        float s0 = dot8(a0,b0,c0,c1);
        float s1 = dot8(a1,b1,c0,c1);
        float s2 = dot8(a2,b2,c0,c1);
        float s3 = dot8(a3,b3,c0,c1);
        #pragma unroll
        for (int o=16; o; o>>=1){
          s0 += __shfl_down_sync(0xffffffffu, s0, o);
          s1 += __shfl_down_sync(0xffffffffu, s1, o);
          s2 += __shfl_down_sync(0xffffffffu, s2, o);
          s3 += __shfl_down_sync(0xffffffffu, s3, o);
        }
        if (lane == 0){
          float lg0 = s0 + sb[r];
          slogit[r] = lg0;
          float nm = fmaxf(wm, lg0);
          wz = wz*__expf(wm-nm) + __expf(lg0-nm); wm = nm;
          if (r1 < myRows){
            float lg = s1 + sb[r1]; slogit[r1] = lg;
            nm = fmaxf(wm, lg); wz = wz*__expf(wm-nm) + __expf(lg-nm); wm = nm;
          }
          if (r2 < myRows){
            float lg = s2 + sb[r2]; slogit[r2] = lg;
            nm = fmaxf(wm, lg); wz = wz*__expf(wm-nm) + __expf(lg-nm); wm = nm;
          }
          if (r3 < myRows){
            float lg = s3 + sb[r3]; slogit[r3] = lg;
            nm = fmaxf(wm, lg); wz = wz*__expf(wm-nm) + __expf(lg-nm); wm = nm;
          }
        }
      }
      if (lane == 0){ swm[warp] = wm; swz[warp] = wz; }
      __syncthreads();

      // block top-10 + best-interesting (fused) ; warp 2 merges softmax stats
      {
        float v = -CUDART_INF_F; int pi = 0x7FFFFFFF;
        if (tid < myRows && s_hist[tid] != 0.f){
          v = slogit[tid];
          pi = ((base + tid) << 1) | (int)s_int[tid];
        }
        {
          float bv = (pi != 0x7FFFFFFF && (pi & 1)) ? v : -CUDART_INF_F;
          int  bpi = (pi != 0x7FFFFFFF && (pi & 1)) ? pi : 0x7FFFFFFF;
          #pragma unroll
          for (int o=16; o; o>>=1){
            float ov = __shfl_down_sync(0xffffffffu, bv, o);
            int   oi = __shfl_down_sync(0xffffffffu, bpi, o);
            if (ov > bv || (ov == bv && oi < bpi)){ bv = ov; bpi = oi; }
          }
          if (lane == 0){ sbiv[warp] = bv; sbii[warp] = bpi; }
        }
        #pragma unroll
        for (int k = 2; k <= 32; k <<= 1){
          #pragma unroll
          for (int j = k >> 1; j > 0; j >>= 1){
            float ov = __shfl_xor_sync(0xffffffffu, v, j);
            int   oi = __shfl_xor_sync(0xffffffffu, pi, j);
            bool up = ((lane & k) == 0);
            bool iAmLow = ((lane & j) == 0);
            bool otherEarlier = (ov > v) || (ov == v && oi < pi);
            bool shouldHoldEarlier = (up == iAmLow);
            if (shouldHoldEarlier == otherEarlier){ v = ov; pi = oi; }
          }
        }
        if (lane < KTOP){ swtv[warp*KTOP + lane] = v; swti[warp*KTOP + lane] = pi; }
        __syncthreads();
        if (warp == 0){
          int ptr = 0;
          float hv = (lane < NWARP) ? swtv[lane*KTOP] : -CUDART_INF_F;
          int   hi = (lane < NWARP) ? swti[lane*KTOP] : 0x7FFFFFFF;
          for (int it = 0; it < KTOP; it++){
            float bv = hv; int bpi = hi; int bsrc = lane;
            #pragma unroll
            for (int o=16; o; o>>=1){
              float ov = __shfl_xor_sync(0xffffffffu, bv, o);
              int   oi = __shfl_xor_sync(0xffffffffu, bpi, o);
              int   os = __shfl_xor_sync(0xffffffffu, bsrc, o);
              if (ov > bv || (ov == bv && oi < bpi)){ bv = ov; bpi = oi; bsrc = os; }
            }
            if (lane == 0){
              g_candv[c*KTOP + it] = bv;
              g_candi[c*KTOP + it] = bpi;
            }
            if (lane == bsrc){
              ptr++;
              hv = (ptr < KTOP) ? swtv[lane*KTOP + ptr] : -CUDART_INF_F;
              hi = (ptr < KTOP) ? swti[lane*KTOP + ptr] : 0x7FFFFFFF;
            }
          }
        } else if (warp == 1){
          float bv = (lane < NWARP) ? sbiv[lane] : -CUDART_INF_F;
          int  bpi = (lane < NWARP) ? sbii[lane] : 0x7FFFFFFF;
          #pragma unroll
          for (int o=8; o; o>>=1){
            float ov = __shfl_down_sync(0xffffffffu, bv, o);
            int   oi = __shfl_down_sync(0xffffffffu, bpi, o);
            if (ov > bv || (ov == bv && oi < bpi)){ bv = ov; bpi = oi; }
          }
          if (lane == 0){ g_biv[c] = bv; g_bii[c] = bpi; }
        } else if (warp == 2){
          // merge per-warp online softmax stats
          float m = (lane < NWARP) ? swm[lane] : -CUDART_INF_F;
          float z = (lane < NWARP) ? swz[lane] : 0.f;
          float gm = m;
          #pragma unroll
          for (int o=8; o; o>>=1) gm = fmaxf(gm, __shfl_xor_sync(0xffffffffu, gm, o));
          z = z * __expf(m - gm);
          #pragma unroll
          for (int o=8; o; o>>=1) z += __shfl_down_sync(0xffffffffu, z, o);
          if (lane == 0){ g_blkmax[c] = gm; g_blksum[c] = z; }
        }
        __syncthreads();
      }
      if (tid == 0) red_release(&g_cnt1, 1u);
    }

    if (c == 0){
      float pv = (tid < H) ? valW[tid] * scell[tid] : 0.f;
      pv = blockSumB(pv, swv);
      if (tid == 0){ WAIT_ACQ(g_cnt1, (unsigned)(NB-1)*(unsigned)(t+1)); }
      __syncthreads();
      float lv[CPT]; int lii[CPT];
      #pragma unroll
      for (int k = 0; k < CPT; k++){
        int i = tid + k*TPB;
        if (i < NCAND){ lv[k] = __ldcg(&g_candv[i]); lii[k] = __ldcg(&g_candi[i]); }
        else { lv[k] = -CUDART_INF_F; lii[k] = 0x7FFFFFFF; }
      }
      // fused dual block-reduction: K1 (all candidates) + I1 (per-block bests)
      float kv = -CUDART_INF_F; int kpi = 0x7FFFFFFF;
      #pragma unroll
      for (int k = 0; k < CPT; k++)
        if (lv[k] > kv || (lv[k] == kv && lii[k] < kpi)){ kv = lv[k]; kpi = lii[k]; }
      float iv = (tid < NB) ? __ldcg(&g_biv[tid]) : -CUDART_INF_F;
      int  ipi = (tid < NB) ? __ldcg(&g_bii[tid]) : 0x7FFFFFFF;
      {
        #pragma unroll
        for (int o=16; o; o>>=1){
          float ov = __shfl_down_sync(0xffffffffu, kv, o);
          int   oi = __shfl_down_sync(0xffffffffu, kpi, o);
          if (ov > kv || (ov == kv && oi < kpi)){ kv = ov; kpi = oi; }
          float ov2 = __shfl_down_sync(0xffffffffu, iv, o);
          int   oi2 = __shfl_down_sync(0xffffffffu, ipi, o);
          if (ov2 > iv || (ov2 == iv && oi2 < ipi)){ iv = ov2; ipi = oi2; }
        }
        if (lane == 0){ swv[warp] = kv; swi[warp] = kpi; swv2[warp] = iv; swi2[warp] = ipi; }
        __syncthreads();
        if (warp == 0){
          float x = (lane < NWARP) ? swv[lane] : -CUDART_INF_F;
          int  xi = (lane < NWARP) ? swi[lane] : 0x7FFFFFFF;
          float y = (lane < NWARP) ? swv2[lane] : -CUDART_INF_F;
          int  yi = (lane < NWARP) ? swi2[lane] : 0x7FFFFFFF;
          #pragma unroll
          for (int o=8; o; o>>=1){
            float ov = __shfl_down_sync(0xffffffffu, x, o);
            int   oi = __shfl_down_sync(0xffffffffu, xi, o);
            if (ov > x || (ov == x && oi < xi)){ x = ov; xi = oi; }
            float ov2 = __shfl_down_sync(0xffffffffu, y, o);
            int   oi2 = __shfl_down_sync(0xffffffffu, yi, o);
            if (ov2 > y || (ov2 == y && oi2 < yi)){ y = ov2; yi = oi2; }
          }
          if (lane == 0){ swv[0] = x; swi[0] = xi; swv2[0] = y; swi2[0] = yi; }
        }
        __syncthreads();
        kv = swv[0]; kpi = swi[0]; iv = swv2[0]; ipi = swi2[0];
        __syncthreads();
      }
      if (tid < 16){
        int row = (tid < 8) ? (kpi >> 1) : ((ipi != 0x7FFFFFFF) ? (ipi >> 1) : (kpi >> 1));
        const float* pa = emb + (size_t)row*H + (tid & 7)*32;
        asm volatile("prefetch.global.L2 [%0];" :: "l"(pa));
      }
      float cnt = 0.f;
      if (ipi != 0x7FFFFFFF){
        #pragma unroll
        for (int k = 0; k < CPT; k++)
          if (lv[k] > iv || (lv[k] == iv && lii[k] < ipi)) cnt += 1.f;
      }
      cnt = blockSumB(cnt, swv);
      if (tid == 0){
        int hit = (ipi != 0x7FFFFFFF) && (cnt <= 9.f);
        unsigned sp = hit ? (unsigned)ipi : ((unsigned)kpi & ~1u);
        int sel = (int)(sp >> 1);
        st_release(&g_selP, ((unsigned)(t+1) << 18) | sp);
        out[OUT_SEL + t] = (float)sel;
        out[OUT_HIT + t] = hit ? 1.f : 0.f;
        out[OUT_VAL + t] = pv + valb[0];
      }
      __syncthreads();
      float bm = -CUDART_INF_F;
      if (tid < NB) bm = __ldcg(&g_blkmax[tid]);
      float gmax = blockMaxB(bm, swv);
      float zz = (tid < NB) ? __ldcg(&g_blksum[tid]) * expf(bm - gmax) : 0.f;
      float Z = blockSumB(zz, swv);
      if (tid == 0){
        g_gmaxS = gmax; g_invZS = 1.f/Z;
        st_release(&g_nrmF, (unsigned)(t+1));
      }
      __syncthreads();
    } else {
      if (tid == 0){
        unsigned sp;
        do { sp = ld_acquire(&g_selP); } while ((sp >> 18) < (unsigned)(t+1));
        int sel = (int)((sp >> 1) & 0x1FFFFu);
        int hit = (int)(sp & 1u);
        s_sel = sel; s_sign = hit ? 1.f : -1.f;
        if (hit && sel >= base && sel < base + myRows) s_hist[sel - base] -= 1.f;
      }
      __syncthreads();

      if (isGru && t < T_STEPS-1){
        if (tid < H) sx[tid] = __ldg(&emb[(size_t)s_sel*H + tid]) * s_sign;
        __syncthreads();
        gru_dots(w0, sx, sgx, gc);
        gru_act(sgx, bih, bhh, g_xb, gc);
        if (tid == 0){ red_release(&g_cntA, 1u); WAIT_ACQ(g_cntA, 86u*(unsigned)(t+2)); }
        __syncthreads();
        if (tid < H) sx[tid] = __ldcg(&g_xb[tid]);
        __syncthreads();
        gru_dots(w1, sx, sgx, gc);
        gru_act(sgx, bih + 3*H, bhh + 3*H, g_xc, gc);
        if (tid == 0){ red_release(&g_cntB, 1u); WAIT_ACQ(g_cntB, 86u*(unsigned)(t+2)); }
        __syncthreads();
        if (tid < H) sx[tid] = __ldcg(&g_xc[tid]);
        __syncthreads();
        if (warp < HPC){
          int h = gc*HPC + warp;
          float s = 0.f;
          if (h < H){
            const float4* wr = (const float4*)(wg + warp*H);
            const float4* xr = (const float4*)sx;
            s = dot8(wr[lane], wr[lane+32], xr[lane], xr[lane+32]);
          }
          #pragma unroll
          for (int o=16; o; o>>=1) s += __shfl_down_sync(0xffffffffu, s, o);
          if (lane == 0) sgx[warp] = s;
        }
        __syncthreads();
        if (tid < HPC){
          int h = gc*HPC + tid;
          if (h < H){
            float gate = sigmoidf_(sgbias[tid] + sgx[tid]);
            g_cell[h] = gate*sprocL[tid] + (1.f-gate)*sx[h];
          }
        }
        __syncthreads();
        if (tid == 0) red_release(&g_cntC, 1u);
      }

      if (tid == 0){
        unsigned nf;
        do { nf = ld_acquire(&g_nrmF); if (nf >= (unsigned)(t+1)) break; __nanosleep(128); } while(1);
        s_gm = __ldcg(&g_gmaxS); s_iz = __ldcg(&g_invZS);
      }
      __syncthreads();

      {
        float gm = s_gm, iz = s_iz;
        for (int i = tid; i < myRows; i += TPB)
          __stcs(&out[(size_t)t*V + base + i], expf(slogit[i]-gm)*iz);
      }
      __syncthreads();
    }
  }

  // ---------- epilogue: hist ----------
  for (int i = tid; i < myRows; i += TPB)
    __stcs(&out[OUT_HIST + base + i], s_hist[i]);
}

extern "C" void kernel_launch(void* const* d_in, const int* in_sizes, int n_in,
                              void* d_out, int out_size){
  (void)in_sizes; (void)n_in; (void)out_size;
  const float* interesting = (const float*)d_in[0];
  const float* masking     = (const float*)d_in[1];
  const float* mem         = (const float*)d_in[2];
  const float* emb         = (const float*)d_in[3];
  const float* Wih         = (const float*)d_in[4];
  /* d_in[5] = gru_Whh unused (hidden state always zero) */
  const float* bih         = (const float*)d_in[6];
  const float* bhh         = (const float*)d_in[7];
  const float* fcW         = (const float*)d_in[8];
  const float* fcb         = (const float*)d_in[9];
  const float* valW        = (const float*)d_in[10];
  const float* valb        = (const float*)d_in[11];
  const float* memW        = (const float*)d_in[12];
  const float* fgmW        = (const float*)d_in[13];
  const float* fgmb        = (const float*)d_in[14];
  const float* fgcW        = (const float*)d_in[15];
  float* out = (float*)d_out;

  static int attr_done = 0;
  if (!attr_done){
    cudaFuncSetAttribute(k_persist, cudaFuncAttributeMaxDynamicSharedMemorySize, DSMEM_BYTES);
    attr_done = 1;
  }
  k_reset<<<1, TPB>>>();
  k_persist<<<NB, TPB, DSMEM_BYTES>>>(interesting, masking, mem, emb, Wih, bih, bhh,
                                      fcW, fcb, valW, valb, memW, fgmW, fgmb, fgcW, out);
}

// round 16
// speedup vs baseline: 1.0538x; 1.0538x over previous
#include <cuda_runtime.h>
#include <math_constants.h>

#define V 100000
#define H 256
#define T_STEPS 64
#define NB 296                /* 2 CTAs per SM; CTA0 = coordinator (no rows) */
#define TPB 512
#define NWARP 16
#define RPC 339               /* 295*339 = 100005 >= V, CTAs 1..295 hold rows */
#define KTOP 10
#define NCAND (NB*KTOP)       /* 2960 */
#define CPT 6                 /* ceil(NCAND/TPB) */
#define HPC 3
#define NGRU 86               /* GRU CTAs: c in [1,86] */
#define SROWS 82              /* fc rows cached in dynamic smem per CTA */
#define DSMEM_BYTES (SROWS*H*4)

#define OUT_SEL   ((size_t)T_STEPS * V)
#define OUT_VAL   (OUT_SEL + T_STEPS)
#define OUT_HIT   (OUT_VAL + T_STEPS)
#define OUT_HIST  (OUT_HIT + T_STEPS)

// ---------------- device scratch ----------------
__device__ __align__(16) float g_cell[H];
__device__ __align__(16) float g_proc[H];
__device__ __align__(16) float g_xb[H];
__device__ __align__(16) float g_xc[H];
__device__ float g_blkmax[NB];
__device__ float g_blksum[NB];
__device__ float g_candv[NCAND];
__device__ int   g_candi[NCAND];      // packed (idx<<1)|interesting
__device__ float g_biv[NB];           // per-block best-interesting value
__device__ int   g_bii[NB];           // per-block best-interesting packed id
__device__ float g_gmaxS, g_invZS;
__device__ unsigned g_selP;           // (t+1)<<18 | (sel<<1) | hit
__device__ unsigned g_cnt0, g_cnt1, g_cntA, g_cntB, g_cntC;
__device__ unsigned g_nrmF;

__device__ __forceinline__ float sigmoidf_(float x){ return 1.f/(1.f+expf(-x)); }
__device__ __forceinline__ float dot8(float4 a, float4 b, float4 x, float4 y){
  return a.x*x.x + a.y*x.y + a.z*x.z + a.w*x.w
       + b.x*y.x + b.y*y.y + b.z*y.z + b.w*y.w;
}

// scoped release/acquire primitives
__device__ __forceinline__ void red_release(unsigned* p, unsigned v){
  asm volatile("red.release.gpu.global.add.u32 [%0], %1;" :: "l"(p), "r"(v) : "memory");
}
__device__ __forceinline__ void st_release(unsigned* p, unsigned v){
  asm volatile("st.release.gpu.global.u32 [%0], %1;" :: "l"(p), "r"(v) : "memory");
}
__device__ __forceinline__ unsigned ld_acquire(unsigned* p){
  unsigned v;
  asm volatile("ld.acquire.gpu.global.u32 %0, [%1];" : "=r"(v) : "l"(p) : "memory");
  return v;
}
#define WAIT_ACQ(ptr, tgt) while (ld_acquire(&(ptr)) < (tgt)) {}

// fc_W loads: L2 evict_last policy (pin resident)
__device__ __forceinline__ float4 ldg_el(const float4* p, unsigned long long pol){
  float4 v;
  asm("ld.global.L2::cache_hint.v4.f32 {%0,%1,%2,%3}, [%4], %5;"
      : "=f"(v.x), "=f"(v.y), "=f"(v.z), "=f"(v.w)
      : "l"(p), "l"(pol));
  return v;
}

__global__ __launch_bounds__(TPB) void k_reset(){
  if (threadIdx.x == 0){
    g_cnt0 = 0u; g_cnt1 = 0u; g_cntA = 0u; g_cntB = 0u; g_cntC = 0u;
    g_selP = 0u; g_nrmF = 0u;
  }
}

// shfl block reductions
__device__ __forceinline__ float blockMaxB(float v, float* sw){
  int lane = threadIdx.x & 31, warp = threadIdx.x >> 5;
  #pragma unroll
  for (int o=16; o; o>>=1) v = fmaxf(v, __shfl_down_sync(0xffffffffu, v, o));
  if (lane == 0) sw[warp] = v;
  __syncthreads();
  if (warp == 0){
    float x = (lane < NWARP) ? sw[lane] : -CUDART_INF_F;
    #pragma unroll
    for (int o=8; o; o>>=1) x = fmaxf(x, __shfl_down_sync(0xffffffffu, x, o));
    if (lane == 0) sw[0] = x;
  }
  __syncthreads();
  float r = sw[0];
  __syncthreads();
  return r;
}
__device__ __forceinline__ float blockSumB(float v, float* sw){
  int lane = threadIdx.x & 31, warp = threadIdx.x >> 5;
  #pragma unroll
  for (int o=16; o; o>>=1) v += __shfl_down_sync(0xffffffffu, v, o);
  if (lane == 0) sw[warp] = v;
  __syncthreads();
  if (warp == 0){
    float x = (lane < NWARP) ? sw[lane] : 0.f;
    #pragma unroll
    for (int o=8; o; o>>=1) x += __shfl_down_sync(0xffffffffu, x, o);
    if (lane == 0) sw[0] = x;
  }
  __syncthreads();
  float r = sw[0];
  __syncthreads();
  return r;
}

// 9 warps: dots for 3 h x 3 gates (weights smem, x smem)
__device__ __forceinline__ void gru_dots(const float* Wsm, const float* sx, float* sgx, int gc){
  int tid = threadIdx.x, lane = tid & 31, warp = tid >> 5;
  if (warp < 3*HPC){
    int a = warp / 3;
    int h = gc*HPC + a;
    float s = 0.f;
    if (h < H){
      const float4* wr = (const float4*)(Wsm + warp*H);
      const float4* xr = (const float4*)sx;
      s = dot8(wr[lane], wr[lane+32], xr[lane], xr[lane+32]);
    }
    #pragma unroll
    for (int o=16; o; o>>=1) s += __shfl_down_sync(0xffffffffu, s, o);
    if (lane == 0) sgx[warp] = s;
  }
  __syncthreads();
}
__device__ __forceinline__ void gru_act(const float* sgx,
                                        const float* bi, const float* bh,
                                        float* xout_g, int gc){
  int tid = threadIdx.x;
  if (tid < HPC){
    int h = gc*HPC + tid;
    if (h < H){
      float r = sigmoidf_(sgx[tid*3+0] + bi[h]     + bh[h]);
      float z = sigmoidf_(sgx[tid*3+1] + bi[H+h]   + bh[H+h]);
      float n = tanhf   (sgx[tid*3+2] + bi[2*H+h] + r*bh[2*H+h]);
      xout_g[h] = (1.f - z) * n;
    }
  }
  __syncthreads();
}

__global__ __launch_bounds__(TPB, 2)
void k_persist(const float* __restrict__ interesting, const float* __restrict__ masking,
               const float* __restrict__ mem, const float* __restrict__ emb,
               const float* __restrict__ Wih, const float* __restrict__ bih,
               const float* __restrict__ bhh, const float* __restrict__ fcW,
               const float* __restrict__ fcb, const float* __restrict__ valW,
               const float* __restrict__ valb, const float* __restrict__ memW,
               const float* __restrict__ fgmW, const float* __restrict__ fgmb,
               const float* __restrict__ fgcW, float* __restrict__ out){
  extern __shared__ __align__(16) float s_wfc[];   // SROWS*H fc rows (dynamic)
  __shared__ __align__(16) float scell[H];
  __shared__ __align__(16) float sx[H];
  __shared__ float sb[RPC];
  __shared__ float slogit[RPC];
  __shared__ float s_hist[RPC];
  __shared__ unsigned char s_int[RPC];
  __shared__ __align__(16) float w0[3*HPC*H];
  __shared__ __align__(16) float w1[3*HPC*H];
  __shared__ __align__(16) float wg[HPC*H];
  __shared__ float swv[NWARP];
  __shared__ int   swi[NWARP];
  __shared__ float swv2[NWARP];
  __shared__ int   swi2[NWARP];
  __shared__ float swtv[NWARP*KTOP];
  __shared__ int   swti[NWARP*KTOP];
  __shared__ float sbiv[NWARP];
  __shared__ int   sbii[NWARP];
  __shared__ float sgx[3*HPC];
  __shared__ float sgbias[HPC];
  __shared__ float sprocL[HPC];
  __shared__ float s_gm, s_iz, s_sign;
  __shared__ int   s_sel;

  const int tid = threadIdx.x, lane = tid & 31, warp = tid >> 5;
  const int c = blockIdx.x;
  const int gc = c - 1;
  const bool isGru = (c >= 1 && c <= NGRU);
  const int base = (c == 0) ? 0 : (c-1) * RPC;
  const int myRows = (c == 0) ? 0 : min(RPC, V - (c-1)*RPC);

  unsigned long long pol;
  asm("createpolicy.fractional.L2::evict_last.b64 %0, 1.0;" : "=l"(pol));

  // ---------- prologue loads ----------
  for (int i = tid; i < myRows; i += TPB){
    sb[i] = fcb[base + i];
    s_hist[i] = masking[base + i];
    s_int[i] = (interesting[base + i] > 0.f) ? 1 : 0;
  }
  if (c != 0){
    const float4* src = (const float4*)(fcW + (size_t)base*H);
    float4* dst = (float4*)s_wfc;
    for (int i = tid; i < SROWS*H/4; i += TPB) dst[i] = __ldcs(&src[i]);
  }
  if (c == 0){
    if (tid == 0){ g_blkmax[0] = -CUDART_INF_F; g_blksum[0] = 0.f;
                   g_biv[0] = -CUDART_INF_F; g_bii[0] = 0x7FFFFFFF; }
    if (tid < KTOP){ g_candv[tid] = -CUDART_INF_F; g_candi[tid] = 0x7FFFFFFF; }
  }
  if (isGru){
    for (int idx = tid; idx < 3*HPC*H; idx += TPB){
      int j = idx / H, col = idx % H;
      int a = j / 3, g = j % 3, h = gc*HPC + a;
      float v0 = 0.f, v1 = 0.f;
      if (h < H){
        v0 = Wih[(size_t)(g*H + h)*H + col];
        v1 = Wih[(size_t)3*H*H + (size_t)(g*H + h)*H + col];
      }
      w0[idx] = v0; w1[idx] = v1;
    }
    for (int idx = tid; idx < HPC*H; idx += TPB){
      int a = idx / H, col = idx % H, h = gc*HPC + a;
      wg[idx] = (h < H) ? fgcW[(size_t)h*H + col] : 0.f;
    }
  }
  // proc row r = c (c < 256)
  for (int r = c; r < H; r += NB){
    const float4* m4 = (const float4*)mem;
    const float4* w4 = (const float4*)(memW + (size_t)r*V);
    float s = 0.f;
    for (int i = tid; i < V/4; i += TPB){
      float4 a = m4[i], b = __ldcs(&w4[i]);
      s += a.x*b.x + a.y*b.y + a.z*b.z + a.w*b.w;
    }
    s = blockSumB(s, swv);
    if (tid == 0){ g_proc[r] = tanhf(s); }
  }
  __syncthreads();
  if (tid == 0) red_release(&g_cnt0, 1u);

  // ---------- prologue GRU: cell(0) from x = emb row 0 ----------
  if (isGru){
    if (tid == 0){ WAIT_ACQ(g_cnt0, (unsigned)NB); }
    __syncthreads();
    if (tid < H) sx[tid] = __ldcg(&g_proc[tid]);
    __syncthreads();
    if (warp < HPC){
      int h = gc*HPC + warp;
      if (h < H){
        const float4* wr = (const float4*)(fgmW + (size_t)h*H);
        const float4* xr = (const float4*)sx;
        float s = dot8(wr[lane], wr[lane+32], xr[lane], xr[lane+32]);
        #pragma unroll
        for (int o=16; o; o>>=1) s += __shfl_down_sync(0xffffffffu, s, o);
        if (lane == 0) sgbias[warp] = -(s + fgmb[h]);
      }
    }
    if (tid < HPC){
      int h = gc*HPC + tid;
      sprocL[tid] = (h < H) ? sx[h] : 0.f;
    }
    __syncthreads();
    if (tid < H) sx[tid] = __ldg(&emb[tid]);
    __syncthreads();
    gru_dots(w0, sx, sgx, gc);
    gru_act(sgx, bih, bhh, g_xb, gc);
    if (tid == 0){ red_release(&g_cntA, 1u); WAIT_ACQ(g_cntA, (unsigned)NGRU); }
    __syncthreads();
    if (tid < H) sx[tid] = __ldcg(&g_xb[tid]);
    __syncthreads();
    gru_dots(w1, sx, sgx, gc);
    gru_act(sgx, bih + 3*H, bhh + 3*H, g_xc, gc);
    if (tid == 0){ red_release(&g_cntB, 1u); WAIT_ACQ(g_cntB, (unsigned)NGRU); }
    __syncthreads();
    if (tid < H) sx[tid] = __ldcg(&g_xc[tid]);
    __syncthreads();
    if (warp < HPC){
      int h = gc*HPC + warp;
      float s = 0.f;
      if (h < H){
        const float4* wr = (const float4*)(wg + warp*H);
        const float4* xr = (const float4*)sx;
        s = dot8(wr[lane], wr[lane+32], xr[lane], xr[lane+32]);
      }
      #pragma unroll
      for (int o=16; o; o>>=1) s += __shfl_down_sync(0xffffffffu, s, o);
      if (lane == 0) sgx[warp] = s;
    }
    __syncthreads();
    if (tid < HPC){
      int h = gc*HPC + tid;
      if (h < H){
        float gate = sigmoidf_(sgbias[tid] + sgx[tid]);
        g_cell[h] = gate*sprocL[tid] + (1.f-gate)*sx[h];
      }
    }
    __syncthreads();
    if (tid == 0) red_release(&g_cntC, 1u);
  }

  // ---------- main loop ----------
  for (int t = 0; t < T_STEPS; t++){
    if (tid == 0){ WAIT_ACQ(g_cntC, 86u*(unsigned)(t+1)); }
    __syncthreads();
    if (tid < H) scell[tid] = __ldcg(&g_cell[tid]);
    __syncthreads();

    if (c != 0){
      const float4* sc4 = (const float4*)scell;
      float4 c0 = sc4[lane], c1 = sc4[lane+32];
      // part 1: smem-resident rows (LDS path, hidden under L2 stream)
      for (int r = warp; r < SROWS; r += NWARP){
        const float4* wr = (const float4*)(s_wfc + r*H);
        float s = dot8(wr[lane], wr[lane+32], c0, c1);
        #pragma unroll
        for (int o=16; o; o>>=1) s += __shfl_down_sync(0xffffffffu, s, o);
        if (lane == 0) slogit[r] = s + sb[r];
      }
      // part 2: L2-resident rows, 4 in flight, evict_last
      for (int r = SROWS + warp; r < myRows; r += NWARP*4){
        int r1 = r + NWARP, r2 = r + 2*NWARP, r3 = r + 3*NWARP;
        int q1 = min(r1, myRows-1), q2 = min(r2, myRows-1), q3 = min(r3, myRows-1);
        const float4* p0 = (const float4*)(fcW + (size_t)(base + r )*H);
        const float4* p1 = (const float4*)(fcW + (size_t)(base + q1)*H);
        const float4* p2 = (const float4*)(fcW + (size_t)(base + q2)*H);
        const float4* p3 = (const float4*)(fcW + (size_t)(base + q3)*H);
        float4 a0 = ldg_el(p0 + lane, pol), b0 = ldg_el(p0 + lane + 32, pol);
        float4 a1 = ldg_el(p1 + lane, pol), b1 = ldg_el(p1 + lane + 32, pol);
        float4 a2 = ldg_el(p2 + lane, pol), b2 = ldg_el(p2 + lane + 32, pol);
        float4 a3 = ldg_el(p3 + lane, pol), b3 = ldg_el(p3 + lane + 32, pol);
        float s0 = dot8(a0,b0,c0,c1);
        float s1 = dot8(a1,b1,c0,c1);
        float s2 = dot8(a2,b2,c0,c1);
        float s3 = dot8(a3,b3,c0,c1);
        #pragma unroll
        for (int o=16; o; o>>=1){
          s0 += __shfl_down_sync(0xffffffffu, s0, o);
          s1 += __shfl_down_sync(0xffffffffu, s1, o);
          s2 += __shfl_down_sync(0xffffffffu, s2, o);
          s3 += __shfl_down_sync(0xffffffffu, s3, o);
        }
        if (lane == 0){
          slogit[r] = s0 + sb[r];
          if (r1 < myRows) slogit[r1] = s1 + sb[r1];
          if (r2 < myRows) slogit[r2] = s2 + sb[r2];
          if (r3 < myRows) slogit[r3] = s3 + sb[r3];
        }
      }
      __syncthreads();

      // block softmax stats (<=1 row per thread)
      {
        float v0 = (tid < myRows) ? slogit[tid] : -CUDART_INF_F;
        float m  = blockMaxB(v0, swv);
        float z  = (tid < myRows) ? expf(v0 - m) : 0.f;
        z = blockSumB(z, swv);
        if (tid == 0){ g_blkmax[c] = m; g_blksum[c] = z; }
      }

      // block top-10 + best-interesting (fused; one syncthreads)
      {
        float v = -CUDART_INF_F; int pi = 0x7FFFFFFF;
        if (tid < myRows && s_hist[tid] != 0.f){
          v = slogit[tid];
          pi = ((base + tid) << 1) | (int)s_int[tid];
        }
        {
          float bv = (pi != 0x7FFFFFFF && (pi & 1)) ? v : -CUDART_INF_F;
          int  bpi = (pi != 0x7FFFFFFF && (pi & 1)) ? pi : 0x7FFFFFFF;
          #pragma unroll
          for (int o=16; o; o>>=1){
            float ov = __shfl_down_sync(0xffffffffu, bv, o);
            int   oi = __shfl_down_sync(0xffffffffu, bpi, o);
            if (ov > bv || (ov == bv && oi < bpi)){ bv = ov; bpi = oi; }
          }
          if (lane == 0){ sbiv[warp] = bv; sbii[warp] = bpi; }
        }
        #pragma unroll
        for (int k = 2; k <= 32; k <<= 1){
          #pragma unroll
          for (int j = k >> 1; j > 0; j >>= 1){
            float ov = __shfl_xor_sync(0xffffffffu, v, j);
            int   oi = __shfl_xor_sync(0xffffffffu, pi, j);
            bool up = ((lane & k) == 0);
            bool iAmLow = ((lane & j) == 0);
            bool otherEarlier = (ov > v) || (ov == v && oi < pi);
            bool shouldHoldEarlier = (up == iAmLow);
            if (shouldHoldEarlier == otherEarlier){ v = ov; pi = oi; }
          }
        }
        if (lane < KTOP){ swtv[warp*KTOP + lane] = v; swti[warp*KTOP + lane] = pi; }
        __syncthreads();
        if (warp == 0){
          int ptr = 0;
          float hv = (lane < NWARP) ? swtv[lane*KTOP] : -CUDART_INF_F;
          int   hi = (lane < NWARP) ? swti[lane*KTOP] : 0x7FFFFFFF;
          for (int it = 0; it < KTOP; it++){
            float bv = hv; int bpi = hi; int bsrc = lane;
            #pragma unroll
            for (int o=16; o; o>>=1){
              float ov = __shfl_xor_sync(0xffffffffu, bv, o);
              int   oi = __shfl_xor_sync(0xffffffffu, bpi, o);
              int   os = __shfl_xor_sync(0xffffffffu, bsrc, o);
              if (ov > bv || (ov == bv && oi < bpi)){ bv = ov; bpi = oi; bsrc = os; }
            }
            if (lane == 0){
              g_candv[c*KTOP + it] = bv;
              g_candi[c*KTOP + it] = bpi;
            }
            if (lane == bsrc){
              ptr++;
              hv = (ptr < KTOP) ? swtv[lane*KTOP + ptr] : -CUDART_INF_F;
              hi = (ptr < KTOP) ? swti[lane*KTOP + ptr] : 0x7FFFFFFF;
            }
          }
        } else if (warp == 1){
          float bv = (lane < NWARP) ? sbiv[lane] : -CUDART_INF_F;
          int  bpi = (lane < NWARP) ? sbii[lane] : 0x7FFFFFFF;
          #pragma unroll
          for (int o=8; o; o>>=1){
            float ov = __shfl_down_sync(0xffffffffu, bv, o);
            int   oi = __shfl_down_sync(0xffffffffu, bpi, o);
            if (ov > bv || (ov == bv && oi < bpi)){ bv = ov; bpi = oi; }
          }
          if (lane == 0){ g_biv[c] = bv; g_bii[c] = bpi; }
        }
        __syncthreads();
      }
      if (tid == 0) red_release(&g_cnt1, 1u);
    }

    if (c == 0){
      float pv = (tid < H) ? valW[tid] * scell[tid] : 0.f;
      pv = blockSumB(pv, swv);
      if (tid == 0){ WAIT_ACQ(g_cnt1, (unsigned)(NB-1)*(unsigned)(t+1)); }
      __syncthreads();
      float lv[CPT]; int lii[CPT];
      #pragma unroll
      for (int k = 0; k < CPT; k++){
        int i = tid + k*TPB;
        if (i < NCAND){ lv[k] = __ldcg(&g_candv[i]); lii[k] = __ldcg(&g_candi[i]); }
        else { lv[k] = -CUDART_INF_F; lii[k] = 0x7FFFFFFF; }
      }
      // fused dual block-reduction: K1 (all candidates) + I1 (per-block bests)
      float kv = -CUDART_INF_F; int kpi = 0x7FFFFFFF;
      #pragma unroll
      for (int k = 0; k < CPT; k++)
        if (lv[k] > kv || (lv[k] == kv && lii[k] < kpi)){ kv = lv[k]; kpi = lii[k]; }
      float iv = (tid < NB) ? __ldcg(&g_biv[tid]) : -CUDART_INF_F;
      int  ipi = (tid < NB) ? __ldcg(&g_bii[tid]) : 0x7FFFFFFF;
      {
        #pragma unroll
        for (int o=16; o; o>>=1){
          float ov = __shfl_down_sync(0xffffffffu, kv, o);
          int   oi = __shfl_down_sync(0xffffffffu, kpi, o);
          if (ov > kv || (ov == kv && oi < kpi)){ kv = ov; kpi = oi; }
          float ov2 = __shfl_down_sync(0xffffffffu, iv, o);
          int   oi2 = __shfl_down_sync(0xffffffffu, ipi, o);
          if (ov2 > iv || (ov2 == iv && oi2 < ipi)){ iv = ov2; ipi = oi2; }
        }
        if (lane == 0){ swv[warp] = kv; swi[warp] = kpi; swv2[warp] = iv; swi2[warp] = ipi; }
        __syncthreads();
        if (warp == 0){
          float x = (lane < NWARP) ? swv[lane] : -CUDART_INF_F;
          int  xi = (lane < NWARP) ? swi[lane] : 0x7FFFFFFF;
          float y = (lane < NWARP) ? swv2[lane] : -CUDART_INF_F;
          int  yi = (lane < NWARP) ? swi2[lane] : 0x7FFFFFFF;
          #pragma unroll
          for (int o=8; o; o>>=1){
            float ov = __shfl_down_sync(0xffffffffu, x, o);
            int   oi = __shfl_down_sync(0xffffffffu, xi, o);
            if (ov > x || (ov == x && oi < xi)){ x = ov; xi = oi; }
            float ov2 = __shfl_down_sync(0xffffffffu, y, o);
            int   oi2 = __shfl_down_sync(0xffffffffu, yi, o);
            if (ov2 > y || (ov2 == y && oi2 < yi)){ y = ov2; yi = oi2; }
          }
          if (lane == 0){ swv[0] = x; swi[0] = xi; swv2[0] = y; swi2[0] = yi; }
        }
        __syncthreads();
        kv = swv[0]; kpi = swi[0]; iv = swv2[0]; ipi = swi2[0];
        __syncthreads();
      }
      if (tid < 16){
        int row = (tid < 8) ? (kpi >> 1) : ((ipi != 0x7FFFFFFF) ? (ipi >> 1) : (kpi >> 1));
        const float* pa = emb + (size_t)row*H + (tid & 7)*32;
        asm volatile("prefetch.global.L2 [%0];" :: "l"(pa));
      }
      float cnt = 0.f;
      if (ipi != 0x7FFFFFFF){
        #pragma unroll
        for (int k = 0; k < CPT; k++)
          if (lv[k] > iv || (lv[k] == iv && lii[k] < ipi)) cnt += 1.f;
      }
      cnt = blockSumB(cnt, swv);
      if (tid == 0){
        int hit = (ipi != 0x7FFFFFFF) && (cnt <= 9.f);
        unsigned sp = hit ? (unsigned)ipi : ((unsigned)kpi & ~1u);
        int sel = (int)(sp >> 1);
        st_release(&g_selP, ((unsigned)(t+1) << 18) | sp);
        out[OUT_SEL + t] = (float)sel;
        out[OUT_HIT + t] = hit ? 1.f : 0.f;
        out[OUT_VAL + t] = pv + valb[0];
      }
      __syncthreads();
      float bm = -CUDART_INF_F;
      if (tid < NB) bm = __ldcg(&g_blkmax[tid]);
      float gmax = blockMaxB(bm, swv);
      float zz = (tid < NB) ? __ldcg(&g_blksum[tid]) * expf(bm - gmax) : 0.f;
      float Z = blockSumB(zz, swv);
      if (tid == 0){
        g_gmaxS = gmax; g_invZS = 1.f/Z;
        st_release(&g_nrmF, (unsigned)(t+1));
      }
      __syncthreads();
    } else {
      if (tid == 0){
        unsigned sp;
        do { sp = ld_acquire(&g_selP); } while ((sp >> 18) < (unsigned)(t+1));
        int sel = (int)((sp >> 1) & 0x1FFFFu);
        int hit = (int)(sp & 1u);
        s_sel = sel; s_sign = hit ? 1.f : -1.f;
        if (hit && sel >= base && sel < base + myRows) s_hist[sel - base] -= 1.f;
      }
      __syncthreads();

      if (isGru && t < T_STEPS-1){
        if (tid < H) sx[tid] = __ldg(&emb[(size_t)s_sel*H + tid]) * s_sign;
        __syncthreads();
        gru_dots(w0, sx, sgx, gc);
        gru_act(sgx, bih, bhh, g_xb, gc);
        if (tid == 0){ red_release(&g_cntA, 1u); WAIT_ACQ(g_cntA, 86u*(unsigned)(t+2)); }
        __syncthreads();
        if (tid < H) sx[tid] = __ldcg(&g_xb[tid]);
        __syncthreads();
        gru_dots(w1, sx, sgx, gc);
        gru_act(sgx, bih + 3*H, bhh + 3*H, g_xc, gc);
        if (tid == 0){ red_release(&g_cntB, 1u); WAIT_ACQ(g_cntB, 86u*(unsigned)(t+2)); }
        __syncthreads();
        if (tid < H) sx[tid] = __ldcg(&g_xc[tid]);
        __syncthreads();
        if (warp < HPC){
          int h = gc*HPC + warp;
          float s = 0.f;
          if (h < H){
            const float4* wr = (const float4*)(wg + warp*H);
            const float4* xr = (const float4*)sx;
            s = dot8(wr[lane], wr[lane+32], xr[lane], xr[lane+32]);
          }
          #pragma unroll
          for (int o=16; o; o>>=1) s += __shfl_down_sync(0xffffffffu, s, o);
          if (lane == 0) sgx[warp] = s;
        }
        __syncthreads();
        if (tid < HPC){
          int h = gc*HPC + tid;
          if (h < H){
            float gate = sigmoidf_(sgbias[tid] + sgx[tid]);
            g_cell[h] = gate*sprocL[tid] + (1.f-gate)*sx[h];
          }
        }
        __syncthreads();
        if (tid == 0) red_release(&g_cntC, 1u);
      }

      if (tid == 0){
        unsigned nf;
        do { nf = ld_acquire(&g_nrmF); if (nf >= (unsigned)(t+1)) break; __nanosleep(128); } while(1);
        s_gm = __ldcg(&g_gmaxS); s_iz = __ldcg(&g_invZS);
      }
      __syncthreads();

      {
        float gm = s_gm, iz = s_iz;
        for (int i = tid; i < myRows; i += TPB)
          __stcs(&out[(size_t)t*V + base + i], expf(slogit[i]-gm)*iz);
      }
      __syncthreads();
    }
  }

  // ---------- epilogue: hist ----------
  for (int i = tid; i < myRows; i += TPB)
    __stcs(&out[OUT_HIST + base + i], s_hist[i]);
}

extern "C" void kernel_launch(void* const* d_in, const int* in_sizes, int n_in,
                              void* d_out, int out_size){
  (void)in_sizes; (void)n_in; (void)out_size;
  const float* interesting = (const float*)d_in[0];
  const float* masking     = (const float*)d_in[1];
  const float* mem         = (const float*)d_in[2];
  const float* emb         = (const float*)d_in[3];
  const float* Wih         = (const float*)d_in[4];
  /* d_in[5] = gru_Whh unused (hidden state always zero) */
  const float* bih         = (const float*)d_in[6];
  const float* bhh         = (const float*)d_in[7];
  const float* fcW         = (const float*)d_in[8];
  const float* fcb         = (const float*)d_in[9];
  const float* valW        = (const float*)d_in[10];
  const float* valb        = (const float*)d_in[11];
  const float* memW        = (const float*)d_in[12];
  const float* fgmW        = (const float*)d_in[13];
  const float* fgmb        = (const float*)d_in[14];
  const float* fgcW        = (const float*)d_in[15];
  float* out = (float*)d_out;

  static int attr_done = 0;
  if (!attr_done){
    cudaFuncSetAttribute(k_persist, cudaFuncAttributeMaxDynamicSharedMemorySize, DSMEM_BYTES);
    attr_done = 1;
  }
  k_reset<<<1, TPB>>>();
  k_persist<<<NB, TPB, DSMEM_BYTES>>>(interesting, masking, mem, emb, Wih, bih, bhh,
                                      fcW, fcb, valW, valb, memW, fgmW, fgmb, fgcW, out);
}

// round 17
// speedup vs baseline: 1.0689x; 1.0143x over previous
#include <cuda_runtime.h>
#include <math_constants.h>

#define V 100000
#define H 256
#define T_STEPS 64
#define NB 296                /* 2 CTAs per SM; CTA0 = coordinator (no rows) */
#define TPB 512
#define NWARP 16
#define KTOP 10
#define NCAND (NB*KTOP)       /* 2960 */
#define CPT 6                 /* ceil(NCAND/TPB) */
#define HPC 3
#define NGRU 86               /* GRU CTAs: c in [1,86] */
#define SR_G 82               /* fc rows in smem, GRU CTAs */
#define SR_N 103              /* fc rows in smem, non-GRU CTAs */
#define RGRU 325              /* total rows, GRU CTAs (82 smem + 243 L2) */
#define RNON 346              /* total rows, non-GRU CTAs (103 smem + 243 L2) */
#define RMAX 346
#define WSZ (3*HPC*H)         /* 2304 floats per GRU layer */
#define DSMEM_BYTES ((2*WSZ + HPC*H + SR_G*H) * 4)   /* = (5376 + 20992)*4 hmm -> computed: 105472 */

#define OUT_SEL   ((size_t)T_STEPS * V)
#define OUT_VAL   (OUT_SEL + T_STEPS)
#define OUT_HIT   (OUT_VAL + T_STEPS)
#define OUT_HIST  (OUT_HIT + T_STEPS)

// ---------------- device scratch ----------------
__device__ __align__(16) float g_cell[H];
__device__ __align__(16) float g_proc[H];
__device__ __align__(16) float g_xb[H];
__device__ __align__(16) float g_xc[H];
__device__ float g_blkmax[NB];
__device__ float g_blksum[NB];
__device__ float g_candv[NCAND];
__device__ int   g_candi[NCAND];      // packed (idx<<1)|interesting
__device__ float g_biv[NB];
__device__ int   g_bii[NB];
__device__ float g_gmaxS, g_invZS;
__device__ unsigned g_selP;           // (t+1)<<18 | (sel<<1) | hit
__device__ unsigned g_cnt0, g_cnt1, g_cntA, g_cntB, g_cntC;
__device__ unsigned g_nrmF;

__device__ __forceinline__ float sigmoidf_(float x){ return 1.f/(1.f+expf(-x)); }
__device__ __forceinline__ float dot8(float4 a, float4 b, float4 x, float4 y){
  return a.x*x.x + a.y*x.y + a.z*x.z + a.w*x.w
       + b.x*y.x + b.y*y.y + b.z*y.z + b.w*y.w;
}

// scoped release/acquire primitives
__device__ __forceinline__ void red_release(unsigned* p, unsigned v){
  asm volatile("red.release.gpu.global.add.u32 [%0], %1;" :: "l"(p), "r"(v) : "memory");
}
__device__ __forceinline__ void st_release(unsigned* p, unsigned v){
  asm volatile("st.release.gpu.global.u32 [%0], %1;" :: "l"(p), "r"(v) : "memory");
}
__device__ __forceinline__ unsigned ld_acquire(unsigned* p){
  unsigned v;
  asm volatile("ld.acquire.gpu.global.u32 %0, [%1];" : "=r"(v) : "l"(p) : "memory");
  return v;
}
#define WAIT_ACQ(ptr, tgt) while (ld_acquire(&(ptr)) < (tgt)) {}

// fc_W loads: L2 evict_last policy (pin resident)
__device__ __forceinline__ float4 ldg_el(const float4* p, unsigned long long pol){
  float4 v;
  asm("ld.global.L2::cache_hint.v4.f32 {%0,%1,%2,%3}, [%4], %5;"
      : "=f"(v.x), "=f"(v.y), "=f"(v.z), "=f"(v.w)
      : "l"(p), "l"(pol));
  return v;
}

__global__ __launch_bounds__(TPB) void k_reset(){
  if (threadIdx.x == 0){
    g_cnt0 = 0u; g_cnt1 = 0u; g_cntA = 0u; g_cntB = 0u; g_cntC = 0u;
    g_selP = 0u; g_nrmF = 0u;
  }
}

// shfl block reductions
__device__ __forceinline__ float blockMaxB(float v, float* sw){
  int lane = threadIdx.x & 31, warp = threadIdx.x >> 5;
  #pragma unroll
  for (int o=16; o; o>>=1) v = fmaxf(v, __shfl_down_sync(0xffffffffu, v, o));
  if (lane == 0) sw[warp] = v;
  __syncthreads();
  if (warp == 0){
    float x = (lane < NWARP) ? sw[lane] : -CUDART_INF_F;
    #pragma unroll
    for (int o=8; o; o>>=1) x = fmaxf(x, __shfl_down_sync(0xffffffffu, x, o));
    if (lane == 0) sw[0] = x;
  }
  __syncthreads();
  float r = sw[0];
  __syncthreads();
  return r;
}
__device__ __forceinline__ float blockSumB(float v, float* sw){
  int lane = threadIdx.x & 31, warp = threadIdx.x >> 5;
  #pragma unroll
  for (int o=16; o; o>>=1) v += __shfl_down_sync(0xffffffffu, v, o);
  if (lane == 0) sw[warp] = v;
  __syncthreads();
  if (warp == 0){
    float x = (lane < NWARP) ? sw[lane] : 0.f;
    #pragma unroll
    for (int o=8; o; o>>=1) x += __shfl_down_sync(0xffffffffu, x, o);
    if (lane == 0) sw[0] = x;
  }
  __syncthreads();
  float r = sw[0];
  __syncthreads();
  return r;
}

// 9 warps: dots for 3 h x 3 gates (weights smem, x smem)
__device__ __forceinline__ void gru_dots(const float* Wsm, const float* sx, float* sgx, int gc){
  int tid = threadIdx.x, lane = tid & 31, warp = tid >> 5;
  if (warp < 3*HPC){
    int a = warp / 3;
    int h = gc*HPC + a;
    float s = 0.f;
    if (h < H){
      const float4* wr = (const float4*)(Wsm + warp*H);
      const float4* xr = (const float4*)sx;
      s = dot8(wr[lane], wr[lane+32], xr[lane], xr[lane+32]);
    }
    #pragma unroll
    for (int o=16; o; o>>=1) s += __shfl_down_sync(0xffffffffu, s, o);
    if (lane == 0) sgx[warp] = s;
  }
  __syncthreads();
}
__device__ __forceinline__ void gru_act(const float* sgx,
                                        const float* bi, const float* bh,
                                        float* xout_g, int gc){
  int tid = threadIdx.x;
  if (tid < HPC){
    int h = gc*HPC + tid;
    if (h < H){
      float r = sigmoidf_(sgx[tid*3+0] + bi[h]     + bh[h]);
      float z = sigmoidf_(sgx[tid*3+1] + bi[H+h]   + bh[H+h]);
      float n = tanhf   (sgx[tid*3+2] + bi[2*H+h] + r*bh[2*H+h]);
      xout_g[h] = (1.f - z) * n;
    }
  }
  __syncthreads();
}

__global__ __launch_bounds__(TPB, 2)
void k_persist(const float* __restrict__ interesting, const float* __restrict__ masking,
               const float* __restrict__ mem, const float* __restrict__ emb,
               const float* __restrict__ Wih, const float* __restrict__ bih,
               const float* __restrict__ bhh, const float* __restrict__ fcW,
               const float* __restrict__ fcb, const float* __restrict__ valW,
               const float* __restrict__ valb, const float* __restrict__ memW,
               const float* __restrict__ fgmW, const float* __restrict__ fgmb,
               const float* __restrict__ fgcW, float* __restrict__ out){
  extern __shared__ __align__(16) float dsm[];   // union: [w0|w1|wg|fc rows] or [fc rows]
  __shared__ __align__(16) float scell[H];
  __shared__ __align__(16) float sx[H];
  __shared__ float sb[RMAX];
  __shared__ float slogit[RMAX];
  __shared__ float s_hist[RMAX];
  __shared__ unsigned char s_int[RMAX];
  __shared__ float swv[NWARP];
  __shared__ int   swi[NWARP];
  __shared__ float swv2[NWARP];
  __shared__ int   swi2[NWARP];
  __shared__ float swtv[NWARP*KTOP];
  __shared__ int   swti[NWARP*KTOP];
  __shared__ float sbiv[NWARP];
  __shared__ int   sbii[NWARP];
  __shared__ float sgx[3*HPC];
  __shared__ float sgbias[HPC];
  __shared__ float sprocL[HPC];
  __shared__ float s_gm, s_iz, s_sign;
  __shared__ int   s_sel;

  const int tid = threadIdx.x, lane = tid & 31, warp = tid >> 5;
  const int c = blockIdx.x;
  const int gc = c - 1;
  const bool isGru = (c >= 1 && c <= NGRU);
  // two-class row layout: GRU CTAs 325 rows, others 346; CTA0 none
  const int base = (c == 0) ? 0 :
                   (isGru ? (c-1)*RGRU : NGRU*RGRU + (c-1-NGRU)*RNON);
  const int rows = (c == 0) ? 0 : (isGru ? RGRU : RNON);
  const int myRows = (c == 0) ? 0 : min(rows, V - base);
  const int sr = (c == 0) ? 0 : (isGru ? SR_G : SR_N);
  // dynamic smem layout
  float* w0   = dsm;
  float* w1   = dsm + WSZ;
  float* wg   = dsm + 2*WSZ;
  float* s_wfc = isGru ? (dsm + 2*WSZ + HPC*H) : dsm;

  unsigned long long pol;
  asm("createpolicy.fractional.L2::evict_last.b64 %0, 1.0;" : "=l"(pol));

  // ---------- prologue loads ----------
  for (int i = tid; i < myRows; i += TPB){
    sb[i] = fcb[base + i];
    s_hist[i] = masking[base + i];
    s_int[i] = (interesting[base + i] > 0.f) ? 1 : 0;
  }
  if (c != 0){
    const float4* src = (const float4*)(fcW + (size_t)base*H);
    float4* dst = (float4*)s_wfc;
    for (int i = tid; i < sr*H/4; i += TPB) dst[i] = __ldcs(&src[i]);
  }
  if (c == 0){
    if (tid == 0){ g_blkmax[0] = -CUDART_INF_F; g_blksum[0] = 0.f;
                   g_biv[0] = -CUDART_INF_F; g_bii[0] = 0x7FFFFFFF; }
    if (tid < KTOP){ g_candv[tid] = -CUDART_INF_F; g_candi[tid] = 0x7FFFFFFF; }
  }
  if (isGru){
    for (int idx = tid; idx < WSZ; idx += TPB){
      int j = idx / H, col = idx % H;
      int a = j / 3, g = j % 3, h = gc*HPC + a;
      float v0 = 0.f, v1 = 0.f;
      if (h < H){
        v0 = Wih[(size_t)(g*H + h)*H + col];
        v1 = Wih[(size_t)3*H*H + (size_t)(g*H + h)*H + col];
      }
      w0[idx] = v0; w1[idx] = v1;
    }
    for (int idx = tid; idx < HPC*H; idx += TPB){
      int a = idx / H, col = idx % H, h = gc*HPC + a;
      wg[idx] = (h < H) ? fgcW[(size_t)h*H + col] : 0.f;
    }
  }
  // proc row r = c (c < 256)
  for (int r = c; r < H; r += NB){
    const float4* m4 = (const float4*)mem;
    const float4* w4 = (const float4*)(memW + (size_t)r*V);
    float s = 0.f;
    for (int i = tid; i < V/4; i += TPB){
      float4 a = m4[i], b = __ldcs(&w4[i]);
      s += a.x*b.x + a.y*b.y + a.z*b.z + a.w*b.w;
    }
    s = blockSumB(s, swv);
    if (tid == 0){ g_proc[r] = tanhf(s); }
  }
  __syncthreads();
  if (tid == 0) red_release(&g_cnt0, 1u);

  // ---------- prologue GRU: cell(0) from x = emb row 0 ----------
  if (isGru){
    if (tid == 0){ WAIT_ACQ(g_cnt0, (unsigned)NB); }
    __syncthreads();
    if (tid < H) sx[tid] = __ldcg(&g_proc[tid]);
    __syncthreads();
    if (warp < HPC){
      int h = gc*HPC + warp;
      if (h < H){
        const float4* wr = (const float4*)(fgmW + (size_t)h*H);
        const float4* xr = (const float4*)sx;
        float s = dot8(wr[lane], wr[lane+32], xr[lane], xr[lane+32]);
        #pragma unroll
        for (int o=16; o; o>>=1) s += __shfl_down_sync(0xffffffffu, s, o);
        if (lane == 0) sgbias[warp] = -(s + fgmb[h]);
      }
    }
    if (tid < HPC){
      int h = gc*HPC + tid;
      sprocL[tid] = (h < H) ? sx[h] : 0.f;
    }
    __syncthreads();
    if (tid < H) sx[tid] = __ldg(&emb[tid]);
    __syncthreads();
    gru_dots(w0, sx, sgx, gc);
    gru_act(sgx, bih, bhh, g_xb, gc);
    if (tid == 0){ red_release(&g_cntA, 1u); WAIT_ACQ(g_cntA, (unsigned)NGRU); }
    __syncthreads();
    if (tid < H) sx[tid] = __ldcg(&g_xb[tid]);
    __syncthreads();
    gru_dots(w1, sx, sgx, gc);
    gru_act(sgx, bih + 3*H, bhh + 3*H, g_xc, gc);
    if (tid == 0){ red_release(&g_cntB, 1u); WAIT_ACQ(g_cntB, (unsigned)NGRU); }
    __syncthreads();
    if (tid < H) sx[tid] = __ldcg(&g_xc[tid]);
    __syncthreads();
    if (warp < HPC){
      int h = gc*HPC + warp;
      float s = 0.f;
      if (h < H){
        const float4* wr = (const float4*)(wg + warp*H);
        const float4* xr = (const float4*)sx;
        s = dot8(wr[lane], wr[lane+32], xr[lane], xr[lane+32]);
      }
      #pragma unroll
      for (int o=16; o; o>>=1) s += __shfl_down_sync(0xffffffffu, s, o);
      if (lane == 0) sgx[warp] = s;
    }
    __syncthreads();
    if (tid < HPC){
      int h = gc*HPC + tid;
      if (h < H){
        float gate = sigmoidf_(sgbias[tid] + sgx[tid]);
        g_cell[h] = gate*sprocL[tid] + (1.f-gate)*sx[h];
      }
    }
    __syncthreads();
    if (tid == 0) red_release(&g_cntC, 1u);
  }

  // ---------- main loop ----------
  for (int t = 0; t < T_STEPS; t++){
    if (tid == 0){ WAIT_ACQ(g_cntC, 86u*(unsigned)(t+1)); }
    __syncthreads();
    if (tid < H) scell[tid] = __ldcg(&g_cell[tid]);
    __syncthreads();

    if (c != 0){
      const float4* sc4 = (const float4*)scell;
      float4 c0 = sc4[lane], c1 = sc4[lane+32];
      // part 1: smem-resident rows
      for (int r = warp; r < sr; r += NWARP){
        const float4* wr = (const float4*)(s_wfc + r*H);
        float s = dot8(wr[lane], wr[lane+32], c0, c1);
        #pragma unroll
        for (int o=16; o; o>>=1) s += __shfl_down_sync(0xffffffffu, s, o);
        if (lane == 0) slogit[r] = s + sb[r];
      }
      // part 2: L2-resident rows, 4 in flight, evict_last
      for (int r = sr + warp; r < myRows; r += NWARP*4){
        int r1 = r + NWARP, r2 = r + 2*NWARP, r3 = r + 3*NWARP;
        int q1 = min(r1, myRows-1), q2 = min(r2, myRows-1), q3 = min(r3, myRows-1);
        const float4* p0 = (const float4*)(fcW + (size_t)(base + r )*H);
        const float4* p1 = (const float4*)(fcW + (size_t)(base + q1)*H);
        const float4* p2 = (const float4*)(fcW + (size_t)(base + q2)*H);
        const float4* p3 = (const float4*)(fcW + (size_t)(base + q3)*H);
        float4 a0 = ldg_el(p0 + lane, pol), b0 = ldg_el(p0 + lane + 32, pol);
        float4 a1 = ldg_el(p1 + lane, pol), b1 = ldg_el(p1 + lane + 32, pol);
        float4 a2 = ldg_el(p2 + lane, pol), b2 = ldg_el(p2 + lane + 32, pol);
        float4 a3 = ldg_el(p3 + lane, pol), b3 = ldg_el(p3 + lane + 32, pol);
        float s0 = dot8(a0,b0,c0,c1);
        float s1 = dot8(a1,b1,c0,c1);
        float s2 = dot8(a2,b2,c0,c1);
        float s3 = dot8(a3,b3,c0,c1);
        #pragma unroll
        for (int o=16; o; o>>=1){
          s0 += __shfl_down_sync(0xffffffffu, s0, o);
          s1 += __shfl_down_sync(0xffffffffu, s1, o);
          s2 += __shfl_down_sync(0xffffffffu, s2, o);
          s3 += __shfl_down_sync(0xffffffffu, s3, o);
        }
        if (lane == 0){
          slogit[r] = s0 + sb[r];
          if (r1 < myRows) slogit[r1] = s1 + sb[r1];
          if (r2 < myRows) slogit[r2] = s2 + sb[r2];
          if (r3 < myRows) slogit[r3] = s3 + sb[r3];
        }
      }
      __syncthreads();

      // block softmax stats (<=1 row per thread)
      {
        float v0 = (tid < myRows) ? slogit[tid] : -CUDART_INF_F;
        float m  = blockMaxB(v0, swv);
        float z  = (tid < myRows) ? expf(v0 - m) : 0.f;
        z = blockSumB(z, swv);
        if (tid == 0){ g_blkmax[c] = m; g_blksum[c] = z; }
      }

      // block top-10 + best-interesting (fused; one syncthreads)
      {
        float v = -CUDART_INF_F; int pi = 0x7FFFFFFF;
        if (tid < myRows && s_hist[tid] != 0.f){
          v = slogit[tid];
          pi = ((base + tid) << 1) | (int)s_int[tid];
        }
        {
          float bv = (pi != 0x7FFFFFFF && (pi & 1)) ? v : -CUDART_INF_F;
          int  bpi = (pi != 0x7FFFFFFF && (pi & 1)) ? pi : 0x7FFFFFFF;
          #pragma unroll
          for (int o=16; o; o>>=1){
            float ov = __shfl_down_sync(0xffffffffu, bv, o);
            int   oi = __shfl_down_sync(0xffffffffu, bpi, o);
            if (ov > bv || (ov == bv && oi < bpi)){ bv = ov; bpi = oi; }
          }
          if (lane == 0){ sbiv[warp] = bv; sbii[warp] = bpi; }
        }
        #pragma unroll
        for (int k = 2; k <= 32; k <<= 1){
          #pragma unroll
          for (int j = k >> 1; j > 0; j >>= 1){
            float ov = __shfl_xor_sync(0xffffffffu, v, j);
            int   oi = __shfl_xor_sync(0xffffffffu, pi, j);
            bool up = ((lane & k) == 0);
            bool iAmLow = ((lane & j) == 0);
            bool otherEarlier = (ov > v) || (ov == v && oi < pi);
            bool shouldHoldEarlier = (up == iAmLow);
            if (shouldHoldEarlier == otherEarlier){ v = ov; pi = oi; }
          }
        }
        if (lane < KTOP){ swtv[warp*KTOP + lane] = v; swti[warp*KTOP + lane] = pi; }
        __syncthreads();
        if (warp == 0){
          int ptr = 0;
          float hv = (lane < NWARP) ? swtv[lane*KTOP] : -CUDART_INF_F;
          int   hi = (lane < NWARP) ? swti[lane*KTOP] : 0x7FFFFFFF;
          for (int it = 0; it < KTOP; it++){
            float bv = hv; int bpi = hi; int bsrc = lane;
            #pragma unroll
            for (int o=16; o; o>>=1){
              float ov = __shfl_xor_sync(0xffffffffu, bv, o);
              int   oi = __shfl_xor_sync(0xffffffffu, bpi, o);
              int   os = __shfl_xor_sync(0xffffffffu, bsrc, o);
              if (ov > bv || (ov == bv && oi < bpi)){ bv = ov; bpi = oi; bsrc = os; }
            }
            if (lane == 0){
              g_candv[c*KTOP + it] = bv;
              g_candi[c*KTOP + it] = bpi;
            }
            if (lane == bsrc){
              ptr++;
              hv = (ptr < KTOP) ? swtv[lane*KTOP + ptr] : -CUDART_INF_F;
              hi = (ptr < KTOP) ? swti[lane*KTOP + ptr] : 0x7FFFFFFF;
            }
          }
        } else if (warp == 1){
          float bv = (lane < NWARP) ? sbiv[lane] : -CUDART_INF_F;
          int  bpi = (lane < NWARP) ? sbii[lane] : 0x7FFFFFFF;
          #pragma unroll
          for (int o=8; o; o>>=1){
            float ov = __shfl_down_sync(0xffffffffu, bv, o);
            int   oi = __shfl_down_sync(0xffffffffu, bpi, o);
            if (ov > bv || (ov == bv && oi < bpi)){ bv = ov; bpi = oi; }
          }
          if (lane == 0){ g_biv[c] = bv; g_bii[c] = bpi; }
        }
        __syncthreads();
      }
      if (tid == 0) red_release(&g_cnt1, 1u);
    }

    if (c == 0){
      float pv = (tid < H) ? valW[tid] * scell[tid] : 0.f;
      pv = blockSumB(pv, swv);
      if (tid == 0){ WAIT_ACQ(g_cnt1, (unsigned)(NB-1)*(unsigned)(t+1)); }
      __syncthreads();
      float lv[CPT]; int lii[CPT];
      #pragma unroll
      for (int k = 0; k < CPT; k++){
        int i = tid + k*TPB;
        if (i < NCAND){ lv[k] = __ldcg(&g_candv[i]); lii[k] = __ldcg(&g_candi[i]); }
        else { lv[k] = -CUDART_INF_F; lii[k] = 0x7FFFFFFF; }
      }
      // fused dual block-reduction: K1 (all candidates) + I1 (per-block bests)
      float kv = -CUDART_INF_F; int kpi = 0x7FFFFFFF;
      #pragma unroll
      for (int k = 0; k < CPT; k++)
        if (lv[k] > kv || (lv[k] == kv && lii[k] < kpi)){ kv = lv[k]; kpi = lii[k]; }
      float iv = (tid < NB) ? __ldcg(&g_biv[tid]) : -CUDART_INF_F;
      int  ipi = (tid < NB) ? __ldcg(&g_bii[tid]) : 0x7FFFFFFF;
      {
        #pragma unroll
        for (int o=16; o; o>>=1){
          float ov = __shfl_down_sync(0xffffffffu, kv, o);
          int   oi = __shfl_down_sync(0xffffffffu, kpi, o);
          if (ov > kv || (ov == kv && oi < kpi)){ kv = ov; kpi = oi; }
          float ov2 = __shfl_down_sync(0xffffffffu, iv, o);
          int   oi2 = __shfl_down_sync(0xffffffffu, ipi, o);
          if (ov2 > iv || (ov2 == iv && oi2 < ipi)){ iv = ov2; ipi = oi2; }
        }
        if (lane == 0){ swv[warp] = kv; swi[warp] = kpi; swv2[warp] = iv; swi2[warp] = ipi; }
        __syncthreads();
        if (warp == 0){
          float x = (lane < NWARP) ? swv[lane] : -CUDART_INF_F;
          int  xi = (lane < NWARP) ? swi[lane] : 0x7FFFFFFF;
          float y = (lane < NWARP) ? swv2[lane] : -CUDART_INF_F;
          int  yi = (lane < NWARP) ? swi2[lane] : 0x7FFFFFFF;
          #pragma unroll
          for (int o=8; o; o>>=1){
            float ov = __shfl_down_sync(0xffffffffu, x, o);
            int   oi = __shfl_down_sync(0xffffffffu, xi, o);
            if (ov > x || (ov == x && oi < xi)){ x = ov; xi = oi; }
            float ov2 = __shfl_down_sync(0xffffffffu, y, o);
            int   oi2 = __shfl_down_sync(0xffffffffu, yi, o);
            if (ov2 > y || (ov2 == y && oi2 < yi)){ y = ov2; yi = oi2; }
          }
          if (lane == 0){ swv[0] = x; swi[0] = xi; swv2[0] = y; swi2[0] = yi; }
        }
        __syncthreads();
        kv = swv[0]; kpi = swi[0]; iv = swv2[0]; ipi = swi2[0];
        __syncthreads();
      }
      if (tid < 16){
        int row = (tid < 8) ? (kpi >> 1) : ((ipi != 0x7FFFFFFF) ? (ipi >> 1) : (kpi >> 1));
        const float* pa = emb + (size_t)row*H + (tid & 7)*32;
        asm volatile("prefetch.global.L2 [%0];" :: "l"(pa));
      }
      float cnt = 0.f;
      if (ipi != 0x7FFFFFFF){
        #pragma unroll
        for (int k = 0; k < CPT; k++)
          if (lv[k] > iv || (lv[k] == iv && lii[k] < ipi)) cnt += 1.f;
      }
      cnt = blockSumB(cnt, swv);
      if (tid == 0){
        int hit = (ipi != 0x7FFFFFFF) && (cnt <= 9.f);
        unsigned sp = hit ? (unsigned)ipi : ((unsigned)kpi & ~1u);
        int sel = (int)(sp >> 1);
        st_release(&g_selP, ((unsigned)(t+1) << 18) | sp);
        out[OUT_SEL + t] = (float)sel;
        out[OUT_HIT + t] = hit ? 1.f : 0.f;
        out[OUT_VAL + t] = pv + valb[0];
      }
      __syncthreads();
      float bm = -CUDART_INF_F;
      if (tid < NB) bm = __ldcg(&g_blkmax[tid]);
      float gmax = blockMaxB(bm, swv);
      float zz = (tid < NB) ? __ldcg(&g_blksum[tid]) * expf(bm - gmax) : 0.f;
      float Z = blockSumB(zz, swv);
      if (tid == 0){
        g_gmaxS = gmax; g_invZS = 1.f/Z;
        st_release(&g_nrmF, (unsigned)(t+1));
      }
      __syncthreads();
    } else {
      if (tid == 0){
        unsigned sp;
        do { sp = ld_acquire(&g_selP); } while ((sp >> 18) < (unsigned)(t+1));
        int sel = (int)((sp >> 1) & 0x1FFFFu);
        int hit = (int)(sp & 1u);
        s_sel = sel; s_sign = hit ? 1.f : -1.f;
        if (hit && sel >= base && sel < base + myRows) s_hist[sel - base] -= 1.f;
      }
      __syncthreads();

      if (isGru && t < T_STEPS-1){
        if (tid < H) sx[tid] = __ldg(&emb[(size_t)s_sel*H + tid]) * s_sign;
        __syncthreads();
        gru_dots(w0, sx, sgx, gc);
        gru_act(sgx, bih, bhh, g_xb, gc);
        if (tid == 0){ red_release(&g_cntA, 1u); WAIT_ACQ(g_cntA, 86u*(unsigned)(t+2)); }
        __syncthreads();
        if (tid < H) sx[tid] = __ldcg(&g_xb[tid]);
        __syncthreads();
        gru_dots(w1, sx, sgx, gc);
        gru_act(sgx, bih + 3*H, bhh + 3*H, g_xc, gc);
        if (tid == 0){ red_release(&g_cntB, 1u); WAIT_ACQ(g_cntB, 86u*(unsigned)(t+2)); }
        __syncthreads();
        if (tid < H) sx[tid] = __ldcg(&g_xc[tid]);
        __syncthreads();
        if (warp < HPC){
          int h = gc*HPC + warp;
          float s = 0.f;
          if (h < H){
            const float4* wr = (const float4*)(wg + warp*H);
            const float4* xr = (const float4*)sx;
            s = dot8(wr[lane], wr[lane+32], xr[lane], xr[lane+32]);
          }
          #pragma unroll
          for (int o=16; o; o>>=1) s += __shfl_down_sync(0xffffffffu, s, o);
          if (lane == 0) sgx[warp] = s;
        }
        __syncthreads();
        if (tid < HPC){
          int h = gc*HPC + tid;
          if (h < H){
            float gate = sigmoidf_(sgbias[tid] + sgx[tid]);
            g_cell[h] = gate*sprocL[tid] + (1.f-gate)*sx[h];
          }
        }
        __syncthreads();
        if (tid == 0) red_release(&g_cntC, 1u);
      }

      if (tid == 0){
        unsigned nf;
        do { nf = ld_acquire(&g_nrmF); if (nf >= (unsigned)(t+1)) break; __nanosleep(128); } while(1);
        s_gm = __ldcg(&g_gmaxS); s_iz = __ldcg(&g_invZS);
      }
      __syncthreads();

      {
        float gm = s_gm, iz = s_iz;
        for (int i = tid; i < myRows; i += TPB)
          __stcs(&out[(size_t)t*V + base + i], expf(slogit[i]-gm)*iz);
      }
      __syncthreads();
    }
  }

  // ---------- epilogue: hist ----------
  for (int i = tid; i < myRows; i += TPB)
    __stcs(&out[OUT_HIST + base + i], s_hist[i]);
}

extern "C" void kernel_launch(void* const* d_in, const int* in_sizes, int n_in,
                              void* d_out, int out_size){
  (void)in_sizes; (void)n_in; (void)out_size;
  const float* interesting = (const float*)d_in[0];
  const float* masking     = (const float*)d_in[1];
  const float* mem         = (const float*)d_in[2];
  const float* emb         = (const float*)d_in[3];
  const float* Wih         = (const float*)d_in[4];
  /* d_in[5] = gru_Whh unused (hidden state always zero) */
  const float* bih         = (const float*)d_in[6];
  const float* bhh         = (const float*)d_in[7];
  const float* fcW         = (const float*)d_in[8];
  const float* fcb         = (const float*)d_in[9];
  const float* valW        = (const float*)d_in[10];
  const float* valb        = (const float*)d_in[11];
  const float* memW        = (const float*)d_in[12];
  const float* fgmW        = (const float*)d_in[13];
  const float* fgmb        = (const float*)d_in[14];
  const float* fgcW        = (const float*)d_in[15];
  float* out = (float*)d_out;

  static int attr_done = 0;
  if (!attr_done){
    cudaFuncSetAttribute(k_persist, cudaFuncAttributeMaxDynamicSharedMemorySize, DSMEM_BYTES);
    attr_done = 1;
  }
  k_reset<<<1, TPB>>>();
  k_persist<<<NB, TPB, DSMEM_BYTES>>>(interesting, masking, mem, emb, Wih, bih, bhh,
                                      fcW, fcb, valW, valb, memW, fgmW, fgmb, fgcW, out);
}